// round 1
// baseline (speedup 1.0000x reference)
#include <cuda_runtime.h>
#include <math.h>

#define NN 6144
#define FIN 256
#define FOUT 64
#define ALPHA 0.2f
#define NNZ_MAX (1 << 20)

// ---------------- scratch (static device globals; no allocations) ------------
__device__ float g_h[NN * FOUT];
__device__ float g_Wh1[NN];
__device__ float g_Wh2[NN];
__device__ int   g_row_cnt[NN];
__device__ int   g_col_cnt[NN];
__device__ int   g_row_ptr[NN + 1];
__device__ int   g_col_ptr[NN + 1];
__device__ int   g_col_fill[NN];
__device__ int   g_csr_col[NNZ_MAX];
__device__ int   g_csc_row[NNZ_MAX];
__device__ unsigned char g_adj2[(size_t)NN * NN];   // 37.75 MB, exact small ints

// ---------------- zero per-launch accumulators -------------------------------
__global__ void k_zero() {
    int t = blockIdx.x * blockDim.x + threadIdx.x;
    if (t < NN) { g_col_cnt[t] = 0; g_col_fill[t] = 0; }
}

// ---------------- pass 1: per-row nnz count + per-col counts -----------------
__global__ void k_count(const float* __restrict__ adj) {
    int w = (blockIdx.x * blockDim.x + threadIdx.x) >> 5;
    int lane = threadIdx.x & 31;
    if (w >= NN) return;
    const float* row = adj + (size_t)w * NN;
    int cnt = 0;
    for (int c = lane; c < NN; c += 32) {
        if (row[c] != 0.0f) { cnt++; atomicAdd(&g_col_cnt[c], 1); }
    }
    #pragma unroll
    for (int o = 16; o; o >>= 1) cnt += __shfl_down_sync(0xffffffffu, cnt, o);
    if (lane == 0) g_row_cnt[w] = cnt;
}

// ---------------- exclusive scans for row_ptr / col_ptr ----------------------
__global__ void k_scan() {
    __shared__ int s[1024];
    const int tid = threadIdx.x;
    const int PER = NN / 1024;   // 6
    // rows
    {
        int base = tid * PER;
        int loc[PER]; int sum = 0;
        #pragma unroll
        for (int q = 0; q < PER; q++) { loc[q] = sum; sum += g_row_cnt[base + q]; }
        s[tid] = sum; __syncthreads();
        for (int off = 1; off < 1024; off <<= 1) {
            int v = (tid >= off) ? s[tid - off] : 0;
            __syncthreads();
            s[tid] += v;
            __syncthreads();
        }
        int pre = tid ? s[tid - 1] : 0;
        #pragma unroll
        for (int q = 0; q < PER; q++) g_row_ptr[base + q] = pre + loc[q];
        if (tid == 1023) g_row_ptr[NN] = s[1023];
        __syncthreads();
    }
    // cols
    {
        int base = tid * PER;
        int loc[PER]; int sum = 0;
        #pragma unroll
        for (int q = 0; q < PER; q++) { loc[q] = sum; sum += g_col_cnt[base + q]; }
        s[tid] = sum; __syncthreads();
        for (int off = 1; off < 1024; off <<= 1) {
            int v = (tid >= off) ? s[tid - off] : 0;
            __syncthreads();
            s[tid] += v;
            __syncthreads();
        }
        int pre = tid ? s[tid - 1] : 0;
        #pragma unroll
        for (int q = 0; q < PER; q++) g_col_ptr[base + q] = pre + loc[q];
        if (tid == 1023) g_col_ptr[NN] = s[1023];
    }
}

// ---------------- pass 2: fill CSR (sorted, deterministic) + CSC -------------
__global__ void k_fill(const float* __restrict__ adj) {
    int w = (blockIdx.x * blockDim.x + threadIdx.x) >> 5;
    int lane = threadIdx.x & 31;
    if (w >= NN) return;
    const float* row = adj + (size_t)w * NN;
    int off = g_row_ptr[w];
    for (int c0 = 0; c0 < NN; c0 += 32) {
        int c = c0 + lane;
        bool nz = row[c] != 0.0f;
        unsigned m = __ballot_sync(0xffffffffu, nz);
        if (nz) {
            int pos = off + __popc(m & ((1u << lane) - 1u));
            g_csr_col[pos] = c;
            int cp = atomicAdd(&g_col_fill[c], 1);
            g_csc_row[g_col_ptr[c] + cp] = w;    // unsorted; consumed in exact int sums only
        }
        off += __popc(m);
    }
}

// ---------------- h = x @ W (tiny 201 MFLOP GEMM) -----------------------------
__global__ void k_gemm(const float* __restrict__ x, const float* __restrict__ W) {
    __shared__ float xs[4][FIN];
    int tid = threadIdx.x;
    int r0 = blockIdx.x * 4;
    for (int q = tid; q < 4 * FIN; q += 256)
        xs[q >> 8][q & 255] = x[(size_t)(r0 + (q >> 8)) * FIN + (q & 255)];
    __syncthreads();
    int r = tid >> 6, c = tid & 63;
    float acc = 0.f;
    #pragma unroll 8
    for (int k = 0; k < FIN; k++) acc += xs[r][k] * __ldg(&W[k * FOUT + c]);
    g_h[(size_t)(r0 + r) * FOUT + c] = acc;
}

// ---------------- Wh1 = h@a[:64], Wh2 = h@a[64:] ------------------------------
__global__ void k_wh(const float* __restrict__ a) {
    int w = (blockIdx.x * blockDim.x + threadIdx.x) >> 5;
    int lane = threadIdx.x & 31;
    if (w >= NN) return;
    float h0 = g_h[(size_t)w * FOUT + lane];
    float h1 = g_h[(size_t)w * FOUT + 32 + lane];
    float v1 = h0 * a[lane]      + h1 * a[32 + lane];
    float v2 = h0 * a[64 + lane] + h1 * a[96 + lane];
    #pragma unroll
    for (int o = 16; o; o >>= 1) {
        v1 += __shfl_down_sync(0xffffffffu, v1, o);
        v2 += __shfl_down_sync(0xffffffffu, v2, o);
    }
    if (lane == 0) { g_Wh1[w] = v1; g_Wh2[w] = v2; }
}

// ---------------- adj2 = adj @ adj, one row per block, SMEM counters ---------
__global__ void k_adj2() {
    __shared__ unsigned int cnt[NN];      // 24 KB
    int i = blockIdx.x;
    int tid = threadIdx.x;
    for (int j = tid; j < NN; j += 256) cnt[j] = 0u;
    __syncthreads();
    int rb = g_row_ptr[i], re = g_row_ptr[i + 1];
    int warp = tid >> 5, lane = tid & 31;
    for (int kk = rb + warp; kk < re; kk += 8) {
        int k = g_csr_col[kk];
        int kb = g_row_ptr[k], ke = g_row_ptr[k + 1];
        for (int t = kb + lane; t < ke; t += 32)
            atomicAdd(&cnt[g_csr_col[t]], 1u);
    }
    __syncthreads();
    unsigned char* out = g_adj2 + (size_t)i * NN;
    for (int j = tid; j < NN; j += 256) out[j] = (unsigned char)cnt[j];
}

// ---------------- fused: adj3@edges + scores + softmax + SpMM + elu ----------
__global__ void k_main(const float* __restrict__ Wsi, const float* __restrict__ Wei,
                       float* __restrict__ out) {
    __shared__ __align__(16) unsigned char s_a2[NN];  // 6 KB: adj2 row i
    __shared__ float s_sc[NN];                        // 24 KB: per-edge scores
    __shared__ float s_red[256];
    __shared__ float s_part[256];

    int i = blockIdx.x, tid = threadIdx.x;

    // load adj2 row (vectorized)
    const uint4* src = (const uint4*)(g_adj2 + (size_t)i * NN);
    uint4* dst = (uint4*)s_a2;
    for (int q = tid; q < NN / 16; q += 256) dst[q] = src[q];
    __syncthreads();

    int rb = g_row_ptr[i];
    int deg = g_row_ptr[i + 1] - rb;
    float aWei = fabsf(*Wei), aWsi = fabsf(*Wsi);
    float wh1 = g_Wh1[i];
    int warp = tid >> 5, lane = tid & 31;

    // scores: warp per edge; adj3[i,j] = sum over in-neighbors k of j of adj2[i,k]
    for (int e = warp; e < deg; e += 8) {
        int j = g_csr_col[rb + e];
        int cb = g_col_ptr[j], ce = g_col_ptr[j + 1];
        unsigned s3 = 0;
        for (int t = cb + lane; t < ce; t += 32) s3 += (unsigned)s_a2[g_csc_row[t]];
        #pragma unroll
        for (int o = 16; o; o >>= 1) s3 += __shfl_down_sync(0xffffffffu, s3, o);
        if (lane == 0) {
            float aw = 1.0f + (float)s_a2[j] + (float)s3;   // adj + adj2 + adj3 at an edge
            float wh = wh1 + g_Wh2[j];
            float lr = wh > 0.f ? wh : ALPHA * wh;
            s_sc[e] = aWei * lr + aWsi * aw;
        }
    }
    __syncthreads();

    // row softmax over neighbors (masked entries underflow to exactly 0 in ref)
    float m = -3.4e38f;
    for (int e = tid; e < deg; e += 256) m = fmaxf(m, s_sc[e]);
    s_red[tid] = m; __syncthreads();
    #pragma unroll
    for (int o = 128; o; o >>= 1) { if (tid < o) s_red[tid] = fmaxf(s_red[tid], s_red[tid + o]); __syncthreads(); }
    m = s_red[0];
    __syncthreads();

    float sum = 0.f;
    for (int e = tid; e < deg; e += 256) { float p = expf(s_sc[e] - m); s_sc[e] = p; sum += p; }
    s_red[tid] = sum; __syncthreads();
    #pragma unroll
    for (int o = 128; o; o >>= 1) { if (tid < o) s_red[tid] += s_red[tid + o]; __syncthreads(); }
    float inv = 1.0f / s_red[0];
    __syncthreads();

    // h_prime[i] = sum_e p_e * h[j_e]; 4 edge-groups x 64 features
    int f = tid & 63, g = tid >> 6;
    float acc = 0.f;
    if (deg > 0) {
        for (int e = g; e < deg; e += 4)
            acc += s_sc[e] * g_h[(size_t)g_csr_col[rb + e] * FOUT + f];
        acc *= inv;
    } else {
        // isolated node: softmax over all-equal -> uniform 1/N over every node
        for (int j = g; j < NN; j += 4) acc += g_h[(size_t)j * FOUT + f];
        acc *= (1.0f / NN);
    }
    s_part[tid] = acc; __syncthreads();
    if (tid < 64) {
        float tot = s_part[tid] + s_part[64 + tid] + s_part[128 + tid] + s_part[192 + tid];
        out[(size_t)i * FOUT + tid] = tot > 0.f ? tot : expm1f(tot);
    }
}

// ---------------- launch ------------------------------------------------------
extern "C" void kernel_launch(void* const* d_in, const int* in_sizes, int n_in,
                              void* d_out, int out_size) {
    const float* x   = (const float*)d_in[0];
    const float* adj = (const float*)d_in[1];
    const float* W   = (const float*)d_in[2];
    const float* a   = (const float*)d_in[3];
    const float* Wsi = (const float*)d_in[4];
    const float* Wei = (const float*)d_in[5];
    float* out = (float*)d_out;

    k_zero <<<(NN + 255) / 256, 256>>>();
    k_count<<<NN / 8, 256>>>(adj);          // 8 warps/block, warp per row
    k_gemm <<<NN / 4, 256>>>(x, W);
    k_wh   <<<NN / 8, 256>>>(a);
    k_scan <<<1, 1024>>>();
    k_fill <<<NN / 8, 256>>>(adj);
    k_adj2 <<<NN, 256>>>();
    k_main <<<NN, 256>>>(Wsi, Wei, out);
}

// round 2
// speedup vs baseline: 1.3223x; 1.3223x over previous
#include <cuda_runtime.h>
#include <math.h>

#define NN 6144
#define FIN 256
#define FOUT 64
#define ALPHA 0.2f
#define NNZ_MAX (1 << 20)
#define NWORDS (NN / 32)      // 192 bitmask words per row
#define DEGMAX 512            // safe cap: deg ~ Binomial(6143, 0.01), mean 61, max ~110

// ---------------- scratch (static device globals; no allocations) ------------
__device__ float g_h[NN * FOUT];
__device__ float g_Wh1[NN];
__device__ float g_Wh2[NN];
__device__ int   g_row_cnt[NN];
__device__ int   g_col_cnt[NN];
__device__ int   g_row_ptr[NN + 1];
__device__ int   g_col_ptr[NN + 1];
__device__ int   g_col_fill[NN];
__device__ int   g_csr_col[NNZ_MAX];
__device__ int   g_csc_row[NNZ_MAX];
__device__ unsigned g_bits[NN * NWORDS];   // 4.7 MB adjacency bitmask

// ---------------- zero per-launch accumulators -------------------------------
__global__ void k_zero() {
    int t = blockIdx.x * blockDim.x + threadIdx.x;
    if (t < NN) { g_col_cnt[t] = 0; g_col_fill[t] = 0; }
}

// ---------------- pass 1: read adj ONCE -> bitmask + row/col counts ----------
__global__ void k_count(const float* __restrict__ adj) {
    int w = (blockIdx.x * blockDim.x + threadIdx.x) >> 5;
    int lane = threadIdx.x & 31;
    if (w >= NN) return;
    const float* row = adj + (size_t)w * NN;
    unsigned* bits = g_bits + (size_t)w * NWORDS;
    int cnt = 0;
    for (int c0 = 0; c0 < NN; c0 += 32) {
        bool nz = row[c0 + lane] != 0.0f;
        unsigned m = __ballot_sync(0xffffffffu, nz);
        if (lane == 0) bits[c0 >> 5] = m;
        cnt += __popc(m);
        if (nz) atomicAdd(&g_col_cnt[c0 + lane], 1);
    }
    if (lane == 0) g_row_cnt[w] = cnt;
}

// ---------------- exclusive scans for row_ptr / col_ptr ----------------------
__global__ void k_scan() {
    __shared__ int s[1024];
    const int tid = threadIdx.x;
    const int PER = NN / 1024;   // 6
    {
        int base = tid * PER;
        int loc[PER]; int sum = 0;
        #pragma unroll
        for (int q = 0; q < PER; q++) { loc[q] = sum; sum += g_row_cnt[base + q]; }
        s[tid] = sum; __syncthreads();
        for (int off = 1; off < 1024; off <<= 1) {
            int v = (tid >= off) ? s[tid - off] : 0;
            __syncthreads();
            s[tid] += v;
            __syncthreads();
        }
        int pre = tid ? s[tid - 1] : 0;
        #pragma unroll
        for (int q = 0; q < PER; q++) g_row_ptr[base + q] = pre + loc[q];
        if (tid == 1023) g_row_ptr[NN] = s[1023];
        __syncthreads();
    }
    {
        int base = tid * PER;
        int loc[PER]; int sum = 0;
        #pragma unroll
        for (int q = 0; q < PER; q++) { loc[q] = sum; sum += g_col_cnt[base + q]; }
        s[tid] = sum; __syncthreads();
        for (int off = 1; off < 1024; off <<= 1) {
            int v = (tid >= off) ? s[tid - off] : 0;
            __syncthreads();
            s[tid] += v;
            __syncthreads();
        }
        int pre = tid ? s[tid - 1] : 0;
        #pragma unroll
        for (int q = 0; q < PER; q++) g_col_ptr[base + q] = pre + loc[q];
        if (tid == 1023) g_col_ptr[NN] = s[1023];
    }
}

// ---------------- pass 2: expand bitmask -> sorted CSR + CSC -----------------
__global__ void k_fill() {
    int w = (blockIdx.x * blockDim.x + threadIdx.x) >> 5;
    int lane = threadIdx.x & 31;
    if (w >= NN) return;
    const unsigned* bits = g_bits + (size_t)w * NWORDS;
    int base = g_row_ptr[w];
    int off = 0;
    #pragma unroll
    for (int it = 0; it < NWORDS / 32; it++) {      // 6 iterations, lane-per-word
        unsigned m = bits[it * 32 + lane];
        int c = __popc(m);
        int pre = c;                                 // inclusive warp scan
        #pragma unroll
        for (int o = 1; o < 32; o <<= 1) {
            int v = __shfl_up_sync(0xffffffffu, pre, o);
            if (lane >= o) pre += v;
        }
        int pos = base + off + (pre - c);
        int col0 = (it * 32 + lane) << 5;
        while (m) {
            int b = __ffs(m) - 1; m &= m - 1;
            int col = col0 + b;
            g_csr_col[pos++] = col;                  // sorted (deterministic order)
            int cp = atomicAdd(&g_col_fill[col], 1);
            g_csc_row[g_col_ptr[col] + cp] = w;      // unsorted; integer sums only
        }
        off += __shfl_sync(0xffffffffu, pre, 31);
    }
}

// ---------------- h = x @ W, fused with Wh1/Wh2 epilogue ----------------------
__global__ void k_gemm(const float* __restrict__ x, const float* __restrict__ W,
                       const float* __restrict__ a) {
    __shared__ float xs[4][FIN];
    __shared__ float red1[8], red2[8];
    int tid = threadIdx.x;
    int r0 = blockIdx.x * 4;
    for (int q = tid; q < 4 * FIN; q += 256)
        xs[q >> 8][q & 255] = x[(size_t)(r0 + (q >> 8)) * FIN + (q & 255)];
    __syncthreads();
    int r = tid >> 6, c = tid & 63;
    float acc = 0.f;
    #pragma unroll 8
    for (int k = 0; k < FIN; k++) acc += xs[r][k] * __ldg(&W[k * FOUT + c]);
    g_h[(size_t)(r0 + r) * FOUT + c] = acc;
    // epilogue: Wh1[row] = h_row . a[:64],  Wh2[row] = h_row . a[64:]
    float v1 = acc * __ldg(&a[c]);
    float v2 = acc * __ldg(&a[64 + c]);
    int lane = tid & 31, warp = tid >> 5;
    #pragma unroll
    for (int o = 16; o; o >>= 1) {
        v1 += __shfl_down_sync(0xffffffffu, v1, o);
        v2 += __shfl_down_sync(0xffffffffu, v2, o);
    }
    if (lane == 0) { red1[warp] = v1; red2[warp] = v2; }
    __syncthreads();
    if (tid < 4) {
        g_Wh1[r0 + tid] = red1[2 * tid] + red1[2 * tid + 1];
        g_Wh2[r0 + tid] = red2[2 * tid] + red2[2 * tid + 1];
    }
}

// ---------------- fused: adj2 row + adj3@edges + softmax + SpMM + elu --------
__global__ void k_fused(const float* __restrict__ Wsi, const float* __restrict__ Wei,
                        float* __restrict__ out) {
    __shared__ unsigned cnt[NN];          // 24 KB: adj2 row i (exact small ints)
    __shared__ float s_sc[DEGMAX];
    __shared__ int   s_j[DEGMAX];
    __shared__ float s_red[256];
    __shared__ float s_part[256];

    int i = blockIdx.x, tid = threadIdx.x;
    int warp = tid >> 5, lane = tid & 31;

    uint4* cz = (uint4*)cnt;
    for (int q = tid; q < NN / 4; q += 256) cz[q] = make_uint4(0, 0, 0, 0);

    int rb = g_row_ptr[i];
    int deg = g_row_ptr[i + 1] - rb;
    for (int e = tid; e < deg; e += 256) s_j[e] = g_csr_col[rb + e];
    __syncthreads();

    // phase 1: adj2 row i  (cnt[j] = #paths i->k->j), warp per neighbor k
    for (int kk = warp; kk < deg; kk += 8) {
        int k = s_j[kk];
        int kb = g_row_ptr[k], ke = g_row_ptr[k + 1];
        for (int t = kb + lane; t < ke; t += 32)
            atomicAdd(&cnt[g_csr_col[t]], 1u);
    }
    __syncthreads();

    // phase 2: per-edge score; adj3[i,j] = sum over in-neighbors k of j of cnt[k]
    float aWei = fabsf(*Wei), aWsi = fabsf(*Wsi);
    float wh1 = g_Wh1[i];
    for (int e = warp; e < deg; e += 8) {
        int j = s_j[e];
        int cb = g_col_ptr[j], ce = g_col_ptr[j + 1];
        unsigned s3 = 0;
        for (int t = cb + lane; t < ce; t += 32) s3 += cnt[g_csc_row[t]];
        #pragma unroll
        for (int o = 16; o; o >>= 1) s3 += __shfl_down_sync(0xffffffffu, s3, o);
        if (lane == 0) {
            float aw = 1.0f + (float)cnt[j] + (float)s3;   // adj + adj2 + adj3
            float wh = wh1 + g_Wh2[j];
            float lr = wh > 0.f ? wh : ALPHA * wh;
            s_sc[e] = aWei * lr + aWsi * aw;
        }
    }
    __syncthreads();

    // phase 3: softmax over neighbors
    float m = -3.4e38f;
    for (int e = tid; e < deg; e += 256) m = fmaxf(m, s_sc[e]);
    s_red[tid] = m; __syncthreads();
    #pragma unroll
    for (int o = 128; o; o >>= 1) { if (tid < o) s_red[tid] = fmaxf(s_red[tid], s_red[tid + o]); __syncthreads(); }
    m = s_red[0];
    __syncthreads();
    float sum = 0.f;
    for (int e = tid; e < deg; e += 256) { float p = expf(s_sc[e] - m); s_sc[e] = p; sum += p; }
    s_red[tid] = sum; __syncthreads();
    #pragma unroll
    for (int o = 128; o; o >>= 1) { if (tid < o) s_red[tid] += s_red[tid + o]; __syncthreads(); }
    float inv = 1.0f / s_red[0];
    __syncthreads();

    // phase 4: h_prime[i] = sum_e p_e * h[j_e]  (4 edge-groups x 64 features)
    int f = tid & 63, g = tid >> 6;
    float acc = 0.f;
    if (deg > 0) {
        for (int e = g; e < deg; e += 4)
            acc += s_sc[e] * g_h[(size_t)s_j[e] * FOUT + f];
        acc *= inv;
    } else {
        for (int j = g; j < NN; j += 4) acc += g_h[(size_t)j * FOUT + f];
        acc *= (1.0f / NN);
    }
    s_part[tid] = acc; __syncthreads();
    if (tid < 64) {
        float tot = s_part[tid] + s_part[64 + tid] + s_part[128 + tid] + s_part[192 + tid];
        out[(size_t)i * FOUT + tid] = tot > 0.f ? tot : expm1f(tot);
    }
}

// ---------------- launch ------------------------------------------------------
extern "C" void kernel_launch(void* const* d_in, const int* in_sizes, int n_in,
                              void* d_out, int out_size) {
    const float* x   = (const float*)d_in[0];
    const float* adj = (const float*)d_in[1];
    const float* W   = (const float*)d_in[2];
    const float* a   = (const float*)d_in[3];
    const float* Wsi = (const float*)d_in[4];
    const float* Wei = (const float*)d_in[5];
    float* out = (float*)d_out;

    k_zero <<<(NN + 255) / 256, 256>>>();
    k_count<<<NN / 8, 256>>>(adj);
    k_gemm <<<NN / 4, 256>>>(x, W, a);
    k_scan <<<1, 1024>>>();
    k_fill <<<NN / 8, 256>>>();
    k_fused<<<NN, 256>>>(Wsi, Wei, out);
}